// round 11
// baseline (speedup 1.0000x reference)
#include <cuda_runtime.h>
#include <cuda_bf16.h>
#include <cstdint>
#include <stdint.h>
#include <math.h>

#define Bb 16
#define Nn 1024
#define Dd 512
#define Kk 8
#define NITER 3
#define NROWCHUNK 32     // gll_attn chunks (32 rows each)
#define NCHUNK 8         // mu_partial n-chunks (128 rows each)

#define Mtot (Bb*Nn)     // 16384
#define Ntot (2*Dd)      // 1024
#define LDA 40           // smem row stride (bf16): 32 + 8 pad, conflict-free ldmatrix
#define TILE_B (128*LDA*2)    // 10240 bytes
#define MMA_SMEM (2*4*TILE_B) // 81920

__device__ __constant__ float c_EPS = 1e-8f;
__device__ __constant__ float c_LNEPS = 1e-5f;
__device__ __constant__ float c_LOG2PI = 1.8378770664093453f;

// ---------------- scratch ----------------------------------------------------
__device__ float g_keys[Mtot*Dd];
__device__ float g_values[Mtot*Dd];
__device__ float g_q[Bb*Kk*Dd];
__device__ float g_sigma[Bb*Kk*Dd];
__device__ float2 g_wq[Bb*Kk*Dd];          // interleaved {w, q*w}
__device__ float g_c1[Bb*Kk];
__device__ float g_mixing[Bb*Kk];
__device__ float g_attn[Bb*Nn*Kk];
__device__ float g_Spart[Bb*NROWCHUNK*Kk];
__device__ float g_mupart[NCHUNK*Bb*Kk*Dd];
__device__ float g_v2part[NCHUNK*Bb*Kk*Dd];
__device__ float g_mu[Bb*Kk*Dd];

__device__ __align__(16) __nv_bfloat16 g_Ahi[Mtot*Dd];
__device__ __align__(16) __nv_bfloat16 g_Alo[Mtot*Dd];
__device__ __align__(16) __nv_bfloat16 g_Bhi[Ntot*Dd];
__device__ __align__(16) __nv_bfloat16 g_Blo[Ntot*Dd];

// ---------------- PTX helpers ------------------------------------------------
__device__ __forceinline__ uint32_t smem_u32(const void* p) {
    uint32_t a;
    asm("{ .reg .u64 t; cvta.to.shared.u64 t, %1; cvt.u32.u64 %0, t; }" : "=r"(a) : "l"(p));
    return a;
}
__device__ __forceinline__ void cpasync16(uint32_t saddr, const void* g) {
    asm volatile("cp.async.ca.shared.global [%0], [%1], 16;" :: "r"(saddr), "l"(g));
}
__device__ __forceinline__ void ldm4(uint32_t* r, uint32_t addr) {
    asm volatile("ldmatrix.sync.aligned.m8n8.x4.shared.b16 {%0,%1,%2,%3}, [%4];"
        : "=r"(r[0]), "=r"(r[1]), "=r"(r[2]), "=r"(r[3]) : "r"(addr));
}
__device__ __forceinline__ void mma16816(float* c, const uint32_t* a, const uint32_t* b) {
    asm volatile(
        "mma.sync.aligned.m16n8k16.row.col.f32.bf16.bf16.f32 "
        "{%0,%1,%2,%3}, {%4,%5,%6,%7}, {%8,%9}, {%0,%1,%2,%3};"
        : "+f"(c[0]), "+f"(c[1]), "+f"(c[2]), "+f"(c[3])
        : "r"(a[0]), "r"(a[1]), "r"(a[2]), "r"(a[3]), "r"(b[0]), "r"(b[1]));
}

// ---------------- K0: LN stats + bf16 hi/lo split ----------------------------
__global__ __launch_bounds__(128) void ln_split(
    const float* __restrict__ E, const float* __restrict__ lng, const float* __restrict__ lnb)
{
    int row = blockIdx.x;
    int t = threadIdx.x;
    float4 v = ((const float4*)(E + (size_t)row * Dd))[t];
    float s = v.x + v.y + v.z + v.w;
    float s2 = v.x*v.x + v.y*v.y + v.z*v.z + v.w*v.w;
    #pragma unroll
    for (int o = 16; o; o >>= 1) {
        s  += __shfl_xor_sync(0xffffffffu, s,  o);
        s2 += __shfl_xor_sync(0xffffffffu, s2, o);
    }
    __shared__ float sh[2][4];
    if ((t & 31) == 0) { sh[0][t >> 5] = s; sh[1][t >> 5] = s2; }
    __syncthreads();
    float S  = sh[0][0] + sh[0][1] + sh[0][2] + sh[0][3];
    float S2 = sh[1][0] + sh[1][1] + sh[1][2] + sh[1][3];
    float m = S / (float)Dd;
    float var = S2 / (float)Dd - m * m;
    float rs = rsqrtf(var + c_LNEPS);

    float4 g4 = ((const float4*)lng)[t];
    float4 b4 = ((const float4*)lnb)[t];
    float y[4];
    y[0] = (v.x - m) * rs * g4.x + b4.x;
    y[1] = (v.y - m) * rs * g4.y + b4.y;
    y[2] = (v.z - m) * rs * g4.z + b4.z;
    y[3] = (v.w - m) * rs * g4.w + b4.w;
    __nv_bfloat16 hi[4], lo[4];
    #pragma unroll
    for (int i = 0; i < 4; i++) {
        hi[i] = __float2bfloat16(y[i]);
        lo[i] = __float2bfloat16(y[i] - __bfloat162float(hi[i]));
    }
    *(uint2*)(g_Ahi + (size_t)row * Dd + t * 4) = *(uint2*)hi;
    *(uint2*)(g_Alo + (size_t)row * Dd + t * 4) = *(uint2*)lo;
}

// ---------------- K1: W^T bf16 hi/lo split -----------------------------------
__global__ void wt_split(const float* __restrict__ Wk, const float* __restrict__ Wv) {
    __shared__ float tile[32][33];
    int n0 = blockIdx.x * 32;
    int k0 = blockIdx.y * 32;
    const float* W = (n0 < Dd) ? Wk : Wv;
    int nc0 = n0 & (Dd - 1);
    int tx = threadIdx.x, ty = threadIdx.y;
    #pragma unroll
    for (int i = ty; i < 32; i += 8)
        tile[i][tx] = W[(size_t)(k0 + i) * Dd + nc0 + tx];
    __syncthreads();
    #pragma unroll
    for (int i = ty; i < 32; i += 8) {
        float x = tile[tx][i];
        __nv_bfloat16 hi = __float2bfloat16(x);
        __nv_bfloat16 lo = __float2bfloat16(x - __bfloat162float(hi));
        g_Bhi[(size_t)(n0 + i) * Dd + k0 + tx] = hi;
        g_Blo[(size_t)(n0 + i) * Dd + k0 + tx] = lo;
    }
}

// ---------------- K2: HMMA bf16x3 GEMM (unchanged; ~170us) -------------------
__global__ __launch_bounds__(256, 2) void mma_kv(
    const float* __restrict__ bk, const float* __restrict__ bv)
{
    extern __shared__ char dsm[];
    int tid = threadIdx.x, lane = tid & 31, wid = tid >> 5;
    int warp_m = wid >> 1, warp_n = wid & 1;
    int n0 = blockIdx.x * 128;
    int m0 = blockIdx.y * 128;

    float acc[2][8][4];
    #pragma unroll
    for (int i = 0; i < 2; i++)
        #pragma unroll
        for (int j = 0; j < 8; j++)
            #pragma unroll
            for (int q = 0; q < 4; q++) acc[i][j][q] = 0.f;

    const int lrow = tid >> 1;
    const int lseg = (tid & 1) * 2;

    #pragma unroll
    for (int j = 0; j < 2; j++) {
        int off = (lseg + j) * 8;
        size_t ao = (size_t)(m0 + lrow) * Dd + off;
        size_t bo = (size_t)(n0 + lrow) * Dd + off;
        uint32_t so = lrow * LDA * 2 + off * 2;
        cpasync16(smem_u32(dsm + 0*TILE_B + so), g_Ahi + ao);
        cpasync16(smem_u32(dsm + 1*TILE_B + so), g_Alo + ao);
        cpasync16(smem_u32(dsm + 2*TILE_B + so), g_Bhi + bo);
        cpasync16(smem_u32(dsm + 3*TILE_B + so), g_Blo + bo);
    }
    asm volatile("cp.async.commit_group;" ::: "memory");

    for (int kc = 0; kc < 16; kc++) {
        int buf = kc & 1;
        char* cur = dsm + buf * 4 * TILE_B;
        if (kc < 15) {
            char* nxt = dsm + (buf ^ 1) * 4 * TILE_B;
            int kn = (kc + 1) * 32;
            #pragma unroll
            for (int j = 0; j < 2; j++) {
                int off = (lseg + j) * 8;
                size_t ao = (size_t)(m0 + lrow) * Dd + kn + off;
                size_t bo = (size_t)(n0 + lrow) * Dd + kn + off;
                uint32_t so = lrow * LDA * 2 + off * 2;
                cpasync16(smem_u32(nxt + 0*TILE_B + so), g_Ahi + ao);
                cpasync16(smem_u32(nxt + 1*TILE_B + so), g_Alo + ao);
                cpasync16(smem_u32(nxt + 2*TILE_B + so), g_Bhi + bo);
                cpasync16(smem_u32(nxt + 3*TILE_B + so), g_Blo + bo);
            }
            asm volatile("cp.async.commit_group;" ::: "memory");
            asm volatile("cp.async.wait_group 1;" ::: "memory");
        } else {
            asm volatile("cp.async.wait_group 0;" ::: "memory");
        }
        __syncthreads();

        const __nv_bfloat16* sAhi = (const __nv_bfloat16*)(cur + 0*TILE_B);
        const __nv_bfloat16* sAlo = (const __nv_bfloat16*)(cur + 1*TILE_B);
        const __nv_bfloat16* sBhi = (const __nv_bfloat16*)(cur + 2*TILE_B);
        const __nv_bfloat16* sBlo = (const __nv_bfloat16*)(cur + 3*TILE_B);

        #pragma unroll
        for (int ks = 0; ks < 2; ks++) {
            uint32_t ahi[2][4], alo[2][4];
            #pragma unroll
            for (int mi = 0; mi < 2; mi++) {
                int row = warp_m * 32 + mi * 16 + (lane & 15);
                int col = ks * 16 + (lane >> 4) * 8;
                ldm4(ahi[mi], smem_u32(&sAhi[row * LDA + col]));
                ldm4(alo[mi], smem_u32(&sAlo[row * LDA + col]));
            }
            #pragma unroll
            for (int h = 0; h < 2; h++) {
                uint32_t bhi[4][2], blo[4][2];
                #pragma unroll
                for (int jj = 0; jj < 2; jj++) {
                    int nrow = warp_n * 64 + h * 32 + jj * 16 + (lane & 7) + ((lane >> 4) << 3);
                    int col = ks * 16 + ((lane >> 3) & 1) * 8;
                    uint32_t r4[4];
                    ldm4(r4, smem_u32(&sBhi[nrow * LDA + col]));
                    bhi[2*jj][0] = r4[0]; bhi[2*jj][1] = r4[1];
                    bhi[2*jj+1][0] = r4[2]; bhi[2*jj+1][1] = r4[3];
                    ldm4(r4, smem_u32(&sBlo[nrow * LDA + col]));
                    blo[2*jj][0] = r4[0]; blo[2*jj][1] = r4[1];
                    blo[2*jj+1][0] = r4[2]; blo[2*jj+1][1] = r4[3];
                }
                #pragma unroll
                for (int mi = 0; mi < 2; mi++)
                    #pragma unroll
                    for (int j2 = 0; j2 < 4; j2++) {
                        int nj = h * 4 + j2;
                        mma16816(acc[mi][nj], ahi[mi], bhi[j2]);
                        mma16816(acc[mi][nj], ahi[mi], blo[j2]);
                        mma16816(acc[mi][nj], alo[mi], bhi[j2]);
                    }
            }
        }
        __syncthreads();
    }

    const bool isK = (n0 < Dd);
    float* Dst = isK ? g_keys : g_values;
    const float* bias = isK ? bk : bv;
    int nbase = (isK ? n0 : n0 - Dd) + warp_n * 64;
    int mbase = m0 + warp_m * 32;
    int r = lane >> 2, cp = 2 * (lane & 3);
    #pragma unroll
    for (int mi = 0; mi < 2; mi++) {
        #pragma unroll
        for (int nj = 0; nj < 8; nj++) {
            int n = nbase + nj * 8 + cp;
            float b0 = bias[n], b1 = bias[n + 1];
            int m = mbase + mi * 16 + r;
            float2 o0 = { acc[mi][nj][0] + b0, acc[mi][nj][1] + b1 };
            float2 o1 = { acc[mi][nj][2] + b0, acc[mi][nj][3] + b1 };
            *(float2*)&Dst[(size_t)m * Dd + n] = o0;
            *(float2*)&Dst[(size_t)(m + 8) * Dd + n] = o1;
        }
    }
}

// ---------------- K3: slots, queries, AND iter-0 prep (w/qw/c1) --------------
__global__ void init_slots_queries(
    const float* __restrict__ noise_init, const float* __restrict__ slots_mu,
    const float* __restrict__ slots_ls,   const float* __restrict__ mix_in,
    const float* __restrict__ Wq,         const float* __restrict__ bq)
{
    int bk_ = blockIdx.x;
    int b = bk_ >> 3, k = bk_ & 7;
    __shared__ float slot[Dd];
    int t = threadIdx.x;
    for (int d = t; d < Dd; d += 128) {
        float sg = expf(slots_ls[k * Dd + d]);
        slot[d] = slots_mu[k * Dd + d] + sg * noise_init[((size_t)b * Kk + k) * Dd + d];
        g_sigma[((size_t)b * Kk + k) * Dd + d] = sg;
    }
    if (t == 0) g_mixing[b * Kk + k] = mix_in[k];
    __syncthreads();
    float slog = 0.f, sqwq = 0.f;
    for (int j = t; j < Dd; j += 128) {
        float acc = bq[j];
        for (int d = 0; d < Dd; d++) acc += slot[d] * Wq[(size_t)d * Dd + j];
        g_q[((size_t)bk_) * Dd + j] = acc;
        float sg = g_sigma[(size_t)bk_ * Dd + j];
        float w = 1.f / (sg * sg + c_EPS);
        g_wq[(size_t)bk_ * Dd + j] = make_float2(w, acc * w);
        slog += logf(fabsf(sg) + c_EPS);
        sqwq += acc * acc * w;
    }
    #pragma unroll
    for (int o = 16; o; o >>= 1) {
        slog += __shfl_xor_sync(0xffffffffu, slog, o);
        sqwq += __shfl_xor_sync(0xffffffffu, sqwq, o);
    }
    __shared__ float sh[2][4];
    if ((t & 31) == 0) { sh[0][t >> 5] = slog; sh[1][t >> 5] = sqwq; }
    __syncthreads();
    if (t == 0) {
        float SL = sh[0][0] + sh[0][1] + sh[0][2] + sh[0][3];
        float SQ = sh[1][0] + sh[1][1] + sh[1][2] + sh[1][3];
        g_c1[bk_] = -0.5f * (float)Dd * c_LOG2PI - 0.5f * SL - 0.5f * SQ;
    }
}

// ---------------- K4: gll + K-normalized attn + colsum partials --------------
__global__ __launch_bounds__(256) void gll_attn() {
    int b = blockIdx.x, chunk = blockIdx.y;
    int t = threadIdx.x, warp = t >> 5, lane = t & 31;
    __shared__ float2 swq[Kk * Dd];     // 32KB: {w, qw} interleaved -> 1 LDS.64
    __shared__ float c1s[Kk], mixs[Kk];
    __shared__ float wcs[8][Kk];
    for (int i = t; i < Kk * Dd; i += 256)
        swq[i] = g_wq[(size_t)b * Kk * Dd + i];
    if (t < Kk) { c1s[t] = g_c1[b * Kk + t]; mixs[t] = g_mixing[b * Kk + t]; }
    __syncthreads();

    float cs = 0.f;
    int rbase = chunk * 32 + warp * 4;
    for (int rr = 0; rr < 4; rr++) {
        int r = rbase + rr;
        const float* krow = g_keys + ((size_t)b * Nn + r) * Dd;
        float kk[Kk], kq[Kk];
        #pragma unroll
        for (int k = 0; k < Kk; k++) { kk[k] = 0.f; kq[k] = 0.f; }
        #pragma unroll
        for (int i = 0; i < 16; i++) {
            int d = lane + 32 * i;
            float kv = krow[d];
            float kv2 = kv * kv;
            #pragma unroll
            for (int k = 0; k < Kk; k++) {
                float2 wq = swq[k * Dd + d];
                kk[k] += kv2 * wq.x;
                kq[k] += kv  * wq.y;
            }
        }
        #pragma unroll
        for (int o = 16; o; o >>= 1)
            #pragma unroll
            for (int k = 0; k < Kk; k++) {
                kk[k] += __shfl_xor_sync(0xffffffffu, kk[k], o);
                kq[k] += __shfl_xor_sync(0xffffffffu, kq[k], o);
            }
        float au[Kk], rsum = 0.f;
        #pragma unroll
        for (int k = 0; k < Kk; k++) {
            float gll = c1s[k] - 0.5f * kk[k] + kq[k];
            au[k] = mixs[k] * gll;
            rsum += au[k];
        }
        float inv = 1.f / rsum;
        if (lane < Kk) {
            float a = au[lane] * inv;
            g_attn[((size_t)b * Nn + r) * Kk + lane] = a;
            cs += a;
        }
    }
    if (lane < Kk) wcs[warp][lane] = cs;
    __syncthreads();
    if (t < Kk) {
        float S = 0.f;
        #pragma unroll
        for (int w = 0; w < 8; w++) S += wcs[w][t];   // fixed order
        g_Spart[((size_t)b * NROWCHUNK + chunk) * Kk + t] = S;
    }
}

// ---------------- K5: mu / E[v^2] partials (vectorized) ----------------------
// grid (Bb, 2, NCHUNK), 128 thr; thread owns 2 d's (d0 = dt*256 + t*2).
__global__ __launch_bounds__(128) void mu_partial() {
    int b = blockIdx.x, dt = blockIdx.y, nc = blockIdx.z, t = threadIdx.x;
    int d0 = dt * 256 + t * 2;
    int n0 = nc * 128;
    __shared__ float4 att4[128][2];
    {
        const float4* src = (const float4*)(g_attn + ((size_t)b * Nn + n0 + t) * Kk);
        att4[t][0] = src[0];
        att4[t][1] = src[1];
    }
    __syncthreads();
    float mu_[Kk][2], v2_[Kk][2];
    #pragma unroll
    for (int k = 0; k < Kk; k++) { mu_[k][0]=0.f; mu_[k][1]=0.f; v2_[k][0]=0.f; v2_[k][1]=0.f; }
    const float* vb = g_values + ((size_t)b * Nn + n0) * Dd + d0;
    for (int i = 0; i < 128; i++) {
        float2 v = *(const float2*)(vb + (size_t)i * Dd);
        float vx2 = v.x * v.x, vy2 = v.y * v.y;
        float4 a0 = att4[i][0], a1 = att4[i][1];
        float a[Kk] = { a0.x, a0.y, a0.z, a0.w, a1.x, a1.y, a1.z, a1.w };
        #pragma unroll
        for (int k = 0; k < Kk; k++) {
            mu_[k][0] += a[k] * v.x;  mu_[k][1] += a[k] * v.y;
            v2_[k][0] += a[k] * vx2;  v2_[k][1] += a[k] * vy2;
        }
    }
    #pragma unroll
    for (int k = 0; k < Kk; k++) {
        size_t idx = (((size_t)nc * Bb + b) * Kk + k) * Dd + d0;
        *(float2*)(g_mupart + idx) = make_float2(mu_[k][0], mu_[k][1]);
        *(float2*)(g_v2part + idx) = make_float2(v2_[k][0], v2_[k][1]);
    }
}

// ---------------- K6: reduce; update + next prep; final -> outputs -----------
__global__ void reduce_update(int final_it, const float* __restrict__ noise_final,
                              float* __restrict__ out) {
    int bk_ = blockIdx.x;
    int b = bk_ >> 3, k = bk_ & 7;
    int t = threadIdx.x;
    float S = 0.f;
    #pragma unroll
    for (int c = 0; c < NROWCHUNK; c++)
        S += g_Spart[((size_t)b * NROWCHUNK + c) * Kk + k];   // fixed order
    float denom = S + c_EPS;
    float s = S / denom;
    float slog = 0.f, sqwq = 0.f;
    for (int d = t; d < Dd; d += 128) {
        float m = 0.f, v2 = 0.f;
        #pragma unroll
        for (int c = 0; c < NCHUNK; c++) {
            size_t idx = (((size_t)c * Bb + b) * Kk + k) * Dd + d;
            m  += g_mupart[idx];
            v2 += g_v2part[idx];
        }
        m  /= denom;
        v2 /= denom;
        float sg = v2 - m * m * (2.f - s);
        if (final_it) {
            float sa = fmaxf(fabsf(sg), c_EPS);
            out[(size_t)bk_ * Dd + d] = m + sa * noise_final[(size_t)bk_ * Dd + d];
        } else {
            float w = 1.f / (sg * sg + c_EPS);
            float q = g_q[(size_t)bk_ * Dd + d];
            g_wq[(size_t)bk_ * Dd + d] = make_float2(w, q * w);
            slog += logf(fabsf(sg) + c_EPS);
            sqwq += q * q * w;
        }
    }
    if (final_it) {
        // transposed attn output: out[BKD + (b*K+k)*N + n] = attn[b][n][k] / denom
        float* ao = out + Bb * Kk * Dd + ((size_t)b * Kk + k) * Nn;
        float inv = 1.f / denom;
        for (int n = t; n < Nn; n += 128)
            ao[n] = g_attn[((size_t)b * Nn + n) * Kk + k] * inv;
        return;
    }
    #pragma unroll
    for (int o = 16; o; o >>= 1) {
        slog += __shfl_xor_sync(0xffffffffu, slog, o);
        sqwq += __shfl_xor_sync(0xffffffffu, sqwq, o);
    }
    __shared__ float sh[2][4];
    if ((t & 31) == 0) { sh[0][t >> 5] = slog; sh[1][t >> 5] = sqwq; }
    __syncthreads();
    if (t == 0) {
        float SL = sh[0][0] + sh[0][1] + sh[0][2] + sh[0][3];
        float SQ = sh[1][0] + sh[1][1] + sh[1][2] + sh[1][3];
        g_c1[bk_] = -0.5f * (float)Dd * c_LOG2PI - 0.5f * SL - 0.5f * SQ;
        g_mixing[bk_] = s / (float)Nn;
    }
}

// ---------------- launcher ---------------------------------------------------
extern "C" void kernel_launch(void* const* d_in, const int* in_sizes, int n_in,
                              void* d_out, int out_size) {
    const float* embeddings = (const float*)d_in[0];
    const float* noise_init = (const float*)d_in[1];
    const float* noise_final= (const float*)d_in[2];
    const float* slots_mu   = (const float*)d_in[3];
    const float* slots_ls   = (const float*)d_in[4];
    const float* mixing     = (const float*)d_in[5];
    const float* Wk = (const float*)d_in[6];
    const float* bk = (const float*)d_in[7];
    const float* Wq = (const float*)d_in[8];
    const float* bq = (const float*)d_in[9];
    const float* Wv = (const float*)d_in[10];
    const float* bv = (const float*)d_in[11];
    const float* lng = (const float*)d_in[12];
    const float* lnb = (const float*)d_in[13];
    float* out = (float*)d_out;

    cudaFuncSetAttribute(mma_kv, cudaFuncAttributeMaxDynamicSharedMemorySize, MMA_SMEM);

    ln_split<<<Mtot, 128>>>(embeddings, lng, lnb);
    wt_split<<<dim3(32, 16), dim3(32, 8)>>>(Wk, Wv);
    init_slots_queries<<<Bb * Kk, 128>>>(noise_init, slots_mu, slots_ls, mixing, Wq, bq);
    mma_kv<<<dim3(Ntot / 128, Mtot / 128), 256, MMA_SMEM>>>(bk, bv);

    for (int it = 0; it < NITER; it++) {
        gll_attn<<<dim3(Bb, NROWCHUNK), 256>>>();
        mu_partial<<<dim3(Bb, 2, NCHUNK), 128>>>();
        reduce_update<<<Bb * Kk, 128>>>(it == NITER - 1 ? 1 : 0, noise_final, out);
    }
}

// round 12
// speedup vs baseline: 1.1153x; 1.1153x over previous
#include <cuda_runtime.h>
#include <cuda_bf16.h>
#include <cstdint>
#include <stdint.h>
#include <math.h>

#define Bb 16
#define Nn 1024
#define Dd 512
#define Kk 8
#define NITER 3
#define NROWCHUNK 32     // gll_attn chunks (32 rows each)
#define NCHUNK 8         // mu_partial n-chunks (128 rows each)

#define Mtot (Bb*Nn)     // 16384
#define Ntot (2*Dd)      // 1024
#define LDA 40           // smem row stride (bf16): 32 + 8 pad, conflict-free ldmatrix
#define TILE_B (128*LDA*2)    // 10240 bytes
#define MMA_SMEM (2*4*TILE_B) // 81920

__device__ __constant__ float c_EPS = 1e-8f;
__device__ __constant__ float c_LNEPS = 1e-5f;
__device__ __constant__ float c_LOG2PI = 1.8378770664093453f;

// ---------------- scratch ----------------------------------------------------
__device__ float g_keys[Mtot*Dd];
__device__ float g_values[Mtot*Dd];
__device__ float g_q[Bb*Kk*Dd];
__device__ float g_sigma[Bb*Kk*Dd];
__device__ float2 g_wq[Bb*Kk*Dd];          // interleaved {w, q*w}
__device__ float g_c1[Bb*Kk];
__device__ float g_mixing[Bb*Kk];
__device__ float g_attn[Bb*Nn*Kk];
__device__ float g_Spart[Bb*NROWCHUNK*Kk];
__device__ float g_mupart[NCHUNK*Bb*Kk*Dd];
__device__ float g_v2part[NCHUNK*Bb*Kk*Dd];

__device__ __align__(16) __nv_bfloat16 g_Ahi[Mtot*Dd];
__device__ __align__(16) __nv_bfloat16 g_Alo[Mtot*Dd];
__device__ __align__(16) __nv_bfloat16 g_Bhi[Ntot*Dd];
__device__ __align__(16) __nv_bfloat16 g_Blo[Ntot*Dd];

// ---------------- PTX helpers ------------------------------------------------
__device__ __forceinline__ uint32_t smem_u32(const void* p) {
    uint32_t a;
    asm("{ .reg .u64 t; cvta.to.shared.u64 t, %1; cvt.u32.u64 %0, t; }" : "=r"(a) : "l"(p));
    return a;
}
__device__ __forceinline__ void cpasync16(uint32_t saddr, const void* g) {
    asm volatile("cp.async.ca.shared.global [%0], [%1], 16;" :: "r"(saddr), "l"(g));
}
__device__ __forceinline__ void ldm4(uint32_t* r, uint32_t addr) {
    asm volatile("ldmatrix.sync.aligned.m8n8.x4.shared.b16 {%0,%1,%2,%3}, [%4];"
        : "=r"(r[0]), "=r"(r[1]), "=r"(r[2]), "=r"(r[3]) : "r"(addr));
}
__device__ __forceinline__ void mma16816(float* c, const uint32_t* a, const uint32_t* b) {
    asm volatile(
        "mma.sync.aligned.m16n8k16.row.col.f32.bf16.bf16.f32 "
        "{%0,%1,%2,%3}, {%4,%5,%6,%7}, {%8,%9}, {%0,%1,%2,%3};"
        : "+f"(c[0]), "+f"(c[1]), "+f"(c[2]), "+f"(c[3])
        : "r"(a[0]), "r"(a[1]), "r"(a[2]), "r"(a[3]), "r"(b[0]), "r"(b[1]));
}

// ---------------- K0: LN stats + bf16 hi/lo split ----------------------------
__global__ __launch_bounds__(128) void ln_split(
    const float* __restrict__ E, const float* __restrict__ lng, const float* __restrict__ lnb)
{
    int row = blockIdx.x;
    int t = threadIdx.x;
    float4 v = ((const float4*)(E + (size_t)row * Dd))[t];
    float s = v.x + v.y + v.z + v.w;
    float s2 = v.x*v.x + v.y*v.y + v.z*v.z + v.w*v.w;
    #pragma unroll
    for (int o = 16; o; o >>= 1) {
        s  += __shfl_xor_sync(0xffffffffu, s,  o);
        s2 += __shfl_xor_sync(0xffffffffu, s2, o);
    }
    __shared__ float sh[2][4];
    if ((t & 31) == 0) { sh[0][t >> 5] = s; sh[1][t >> 5] = s2; }
    __syncthreads();
    float S  = sh[0][0] + sh[0][1] + sh[0][2] + sh[0][3];
    float S2 = sh[1][0] + sh[1][1] + sh[1][2] + sh[1][3];
    float m = S / (float)Dd;
    float var = S2 / (float)Dd - m * m;
    float rs = rsqrtf(var + c_LNEPS);

    float4 g4 = ((const float4*)lng)[t];
    float4 b4 = ((const float4*)lnb)[t];
    float y[4];
    y[0] = (v.x - m) * rs * g4.x + b4.x;
    y[1] = (v.y - m) * rs * g4.y + b4.y;
    y[2] = (v.z - m) * rs * g4.z + b4.z;
    y[3] = (v.w - m) * rs * g4.w + b4.w;
    __nv_bfloat16 hi[4], lo[4];
    #pragma unroll
    for (int i = 0; i < 4; i++) {
        hi[i] = __float2bfloat16(y[i]);
        lo[i] = __float2bfloat16(y[i] - __bfloat162float(hi[i]));
    }
    *(uint2*)(g_Ahi + (size_t)row * Dd + t * 4) = *(uint2*)hi;
    *(uint2*)(g_Alo + (size_t)row * Dd + t * 4) = *(uint2*)lo;
}

// ---------------- K1: W^T bf16 hi/lo split -----------------------------------
__global__ void wt_split(const float* __restrict__ Wk, const float* __restrict__ Wv) {
    __shared__ float tile[32][33];
    int n0 = blockIdx.x * 32;
    int k0 = blockIdx.y * 32;
    const float* W = (n0 < Dd) ? Wk : Wv;
    int nc0 = n0 & (Dd - 1);
    int tx = threadIdx.x, ty = threadIdx.y;
    #pragma unroll
    for (int i = ty; i < 32; i += 8)
        tile[i][tx] = W[(size_t)(k0 + i) * Dd + nc0 + tx];
    __syncthreads();
    #pragma unroll
    for (int i = ty; i < 32; i += 8) {
        float x = tile[tx][i];
        __nv_bfloat16 hi = __float2bfloat16(x);
        __nv_bfloat16 lo = __float2bfloat16(x - __bfloat162float(hi));
        g_Bhi[(size_t)(n0 + i) * Dd + k0 + tx] = hi;
        g_Blo[(size_t)(n0 + i) * Dd + k0 + tx] = lo;
    }
}

// ---------------- K2: HMMA bf16x3 GEMM (unchanged; ~170us) -------------------
__global__ __launch_bounds__(256, 2) void mma_kv(
    const float* __restrict__ bk, const float* __restrict__ bv)
{
    extern __shared__ char dsm[];
    int tid = threadIdx.x, lane = tid & 31, wid = tid >> 5;
    int warp_m = wid >> 1, warp_n = wid & 1;
    int n0 = blockIdx.x * 128;
    int m0 = blockIdx.y * 128;

    float acc[2][8][4];
    #pragma unroll
    for (int i = 0; i < 2; i++)
        #pragma unroll
        for (int j = 0; j < 8; j++)
            #pragma unroll
            for (int q = 0; q < 4; q++) acc[i][j][q] = 0.f;

    const int lrow = tid >> 1;
    const int lseg = (tid & 1) * 2;

    #pragma unroll
    for (int j = 0; j < 2; j++) {
        int off = (lseg + j) * 8;
        size_t ao = (size_t)(m0 + lrow) * Dd + off;
        size_t bo = (size_t)(n0 + lrow) * Dd + off;
        uint32_t so = lrow * LDA * 2 + off * 2;
        cpasync16(smem_u32(dsm + 0*TILE_B + so), g_Ahi + ao);
        cpasync16(smem_u32(dsm + 1*TILE_B + so), g_Alo + ao);
        cpasync16(smem_u32(dsm + 2*TILE_B + so), g_Bhi + bo);
        cpasync16(smem_u32(dsm + 3*TILE_B + so), g_Blo + bo);
    }
    asm volatile("cp.async.commit_group;" ::: "memory");

    for (int kc = 0; kc < 16; kc++) {
        int buf = kc & 1;
        char* cur = dsm + buf * 4 * TILE_B;
        if (kc < 15) {
            char* nxt = dsm + (buf ^ 1) * 4 * TILE_B;
            int kn = (kc + 1) * 32;
            #pragma unroll
            for (int j = 0; j < 2; j++) {
                int off = (lseg + j) * 8;
                size_t ao = (size_t)(m0 + lrow) * Dd + kn + off;
                size_t bo = (size_t)(n0 + lrow) * Dd + kn + off;
                uint32_t so = lrow * LDA * 2 + off * 2;
                cpasync16(smem_u32(nxt + 0*TILE_B + so), g_Ahi + ao);
                cpasync16(smem_u32(nxt + 1*TILE_B + so), g_Alo + ao);
                cpasync16(smem_u32(nxt + 2*TILE_B + so), g_Bhi + bo);
                cpasync16(smem_u32(nxt + 3*TILE_B + so), g_Blo + bo);
            }
            asm volatile("cp.async.commit_group;" ::: "memory");
            asm volatile("cp.async.wait_group 1;" ::: "memory");
        } else {
            asm volatile("cp.async.wait_group 0;" ::: "memory");
        }
        __syncthreads();

        const __nv_bfloat16* sAhi = (const __nv_bfloat16*)(cur + 0*TILE_B);
        const __nv_bfloat16* sAlo = (const __nv_bfloat16*)(cur + 1*TILE_B);
        const __nv_bfloat16* sBhi = (const __nv_bfloat16*)(cur + 2*TILE_B);
        const __nv_bfloat16* sBlo = (const __nv_bfloat16*)(cur + 3*TILE_B);

        #pragma unroll
        for (int ks = 0; ks < 2; ks++) {
            uint32_t ahi[2][4], alo[2][4];
            #pragma unroll
            for (int mi = 0; mi < 2; mi++) {
                int row = warp_m * 32 + mi * 16 + (lane & 15);
                int col = ks * 16 + (lane >> 4) * 8;
                ldm4(ahi[mi], smem_u32(&sAhi[row * LDA + col]));
                ldm4(alo[mi], smem_u32(&sAlo[row * LDA + col]));
            }
            #pragma unroll
            for (int h = 0; h < 2; h++) {
                uint32_t bhi[4][2], blo[4][2];
                #pragma unroll
                for (int jj = 0; jj < 2; jj++) {
                    int nrow = warp_n * 64 + h * 32 + jj * 16 + (lane & 7) + ((lane >> 4) << 3);
                    int col = ks * 16 + ((lane >> 3) & 1) * 8;
                    uint32_t r4[4];
                    ldm4(r4, smem_u32(&sBhi[nrow * LDA + col]));
                    bhi[2*jj][0] = r4[0]; bhi[2*jj][1] = r4[1];
                    bhi[2*jj+1][0] = r4[2]; bhi[2*jj+1][1] = r4[3];
                    ldm4(r4, smem_u32(&sBlo[nrow * LDA + col]));
                    blo[2*jj][0] = r4[0]; blo[2*jj][1] = r4[1];
                    blo[2*jj+1][0] = r4[2]; blo[2*jj+1][1] = r4[3];
                }
                #pragma unroll
                for (int mi = 0; mi < 2; mi++)
                    #pragma unroll
                    for (int j2 = 0; j2 < 4; j2++) {
                        int nj = h * 4 + j2;
                        mma16816(acc[mi][nj], ahi[mi], bhi[j2]);
                        mma16816(acc[mi][nj], ahi[mi], blo[j2]);
                        mma16816(acc[mi][nj], alo[mi], bhi[j2]);
                    }
            }
        }
        __syncthreads();
    }

    const bool isK = (n0 < Dd);
    float* Dst = isK ? g_keys : g_values;
    const float* bias = isK ? bk : bv;
    int nbase = (isK ? n0 : n0 - Dd) + warp_n * 64;
    int mbase = m0 + warp_m * 32;
    int r = lane >> 2, cp = 2 * (lane & 3);
    #pragma unroll
    for (int mi = 0; mi < 2; mi++) {
        #pragma unroll
        for (int nj = 0; nj < 8; nj++) {
            int n = nbase + nj * 8 + cp;
            float b0 = bias[n], b1 = bias[n + 1];
            int m = mbase + mi * 16 + r;
            float2 o0 = { acc[mi][nj][0] + b0, acc[mi][nj][1] + b1 };
            float2 o1 = { acc[mi][nj][2] + b0, acc[mi][nj][3] + b1 };
            *(float2*)&Dst[(size_t)m * Dd + n] = o0;
            *(float2*)&Dst[(size_t)(m + 8) * Dd + n] = o1;
        }
    }
}

// ---------------- K3: slots, queries, AND iter-0 prep (w/qw/c1) --------------
__global__ void init_slots_queries(
    const float* __restrict__ noise_init, const float* __restrict__ slots_mu,
    const float* __restrict__ slots_ls,   const float* __restrict__ mix_in,
    const float* __restrict__ Wq,         const float* __restrict__ bq)
{
    int bk_ = blockIdx.x;
    int b = bk_ >> 3, k = bk_ & 7;
    __shared__ float slot[Dd];
    int t = threadIdx.x;
    for (int d = t; d < Dd; d += 128) {
        float sg = expf(slots_ls[k * Dd + d]);
        slot[d] = slots_mu[k * Dd + d] + sg * noise_init[((size_t)b * Kk + k) * Dd + d];
        g_sigma[((size_t)b * Kk + k) * Dd + d] = sg;
    }
    if (t == 0) g_mixing[b * Kk + k] = mix_in[k];
    __syncthreads();
    float slog = 0.f, sqwq = 0.f;
    for (int j = t; j < Dd; j += 128) {
        float acc = bq[j];
        for (int d = 0; d < Dd; d++) acc += slot[d] * Wq[(size_t)d * Dd + j];
        g_q[((size_t)bk_) * Dd + j] = acc;
        float sg = g_sigma[(size_t)bk_ * Dd + j];
        float w = 1.f / (sg * sg + c_EPS);
        g_wq[(size_t)bk_ * Dd + j] = make_float2(w, acc * w);
        slog += logf(fabsf(sg) + c_EPS);
        sqwq += acc * acc * w;
    }
    #pragma unroll
    for (int o = 16; o; o >>= 1) {
        slog += __shfl_xor_sync(0xffffffffu, slog, o);
        sqwq += __shfl_xor_sync(0xffffffffu, sqwq, o);
    }
    __shared__ float sh[2][4];
    if ((t & 31) == 0) { sh[0][t >> 5] = slog; sh[1][t >> 5] = sqwq; }
    __syncthreads();
    if (t == 0) {
        float SL = sh[0][0] + sh[0][1] + sh[0][2] + sh[0][3];
        float SQ = sh[1][0] + sh[1][1] + sh[1][2] + sh[1][3];
        g_c1[bk_] = -0.5f * (float)Dd * c_LOG2PI - 0.5f * SL - 0.5f * SQ;
    }
}

// ---------------- K4: gll + attn, 4-row amortized, single accumulator --------
// acc[r][k] = sum_d  kv*qw - 0.5*kv^2*w  (one swq load serves 4 rows)
__global__ __launch_bounds__(256) void gll_attn() {
    int b = blockIdx.x, chunk = blockIdx.y;
    int t = threadIdx.x, warp = t >> 5, lane = t & 31;
    __shared__ float2 swq[Kk * Dd];     // 32KB
    __shared__ float c1s[Kk], mixs[Kk];
    __shared__ float wcs[8][Kk];
    for (int i = t; i < Kk * Dd; i += 256)
        swq[i] = g_wq[(size_t)b * Kk * Dd + i];
    if (t < Kk) { c1s[t] = g_c1[b * Kk + t]; mixs[t] = g_mixing[b * Kk + t]; }
    __syncthreads();

    int rbase = chunk * 32 + warp * 4;
    const float* kb = g_keys + ((size_t)b * Nn + rbase) * Dd;

    float acc[4][Kk];
    #pragma unroll
    for (int r = 0; r < 4; r++)
        #pragma unroll
        for (int k = 0; k < Kk; k++) acc[r][k] = 0.f;

    #pragma unroll
    for (int i = 0; i < 16; i++) {
        int d = lane + 32 * i;
        float kv0 = kb[d], kv1 = kb[Dd + d], kv2 = kb[2*Dd + d], kv3 = kb[3*Dd + d];
        float h0 = -0.5f*kv0*kv0, h1 = -0.5f*kv1*kv1, h2 = -0.5f*kv2*kv2, h3 = -0.5f*kv3*kv3;
        #pragma unroll
        for (int k = 0; k < Kk; k++) {
            float2 wq = swq[k * Dd + d];
            acc[0][k] = fmaf(kv0, wq.y, fmaf(h0, wq.x, acc[0][k]));
            acc[1][k] = fmaf(kv1, wq.y, fmaf(h1, wq.x, acc[1][k]));
            acc[2][k] = fmaf(kv2, wq.y, fmaf(h2, wq.x, acc[2][k]));
            acc[3][k] = fmaf(kv3, wq.y, fmaf(h3, wq.x, acc[3][k]));
        }
    }
    #pragma unroll
    for (int o = 16; o; o >>= 1)
        #pragma unroll
        for (int r = 0; r < 4; r++)
            #pragma unroll
            for (int k = 0; k < Kk; k++)
                acc[r][k] += __shfl_xor_sync(0xffffffffu, acc[r][k], o);

    float cs = 0.f;
    #pragma unroll
    for (int r = 0; r < 4; r++) {
        float au[Kk], rsum = 0.f;
        #pragma unroll
        for (int k = 0; k < Kk; k++) {
            au[k] = mixs[k] * (c1s[k] + acc[r][k]);
            rsum += au[k];
        }
        float inv = 1.f / rsum;
        if (lane < Kk) {
            float a = au[lane] * inv;
            g_attn[((size_t)b * Nn + rbase + r) * Kk + lane] = a;
            cs += a;
        }
    }
    if (lane < Kk) wcs[warp][lane] = cs;
    __syncthreads();
    if (t < Kk) {
        float S = 0.f;
        #pragma unroll
        for (int w = 0; w < 8; w++) S += wcs[w][t];   // fixed order
        g_Spart[((size_t)b * NROWCHUNK + chunk) * Kk + t] = S;
    }
}

// ---------------- K5: mu / E[v^2] partials -----------------------------------
__global__ __launch_bounds__(128) void mu_partial() {
    int b = blockIdx.x, dt = blockIdx.y, nc = blockIdx.z, t = threadIdx.x;
    int d0 = dt * 256 + t * 2;
    int n0 = nc * 128;
    __shared__ float4 att4[128][2];
    {
        const float4* src = (const float4*)(g_attn + ((size_t)b * Nn + n0 + t) * Kk);
        att4[t][0] = src[0];
        att4[t][1] = src[1];
    }
    __syncthreads();
    float mu_[Kk][2], v2_[Kk][2];
    #pragma unroll
    for (int k = 0; k < Kk; k++) { mu_[k][0]=0.f; mu_[k][1]=0.f; v2_[k][0]=0.f; v2_[k][1]=0.f; }
    const float* vb = g_values + ((size_t)b * Nn + n0) * Dd + d0;
    for (int i = 0; i < 128; i++) {
        float2 v = *(const float2*)(vb + (size_t)i * Dd);
        float vx2 = v.x * v.x, vy2 = v.y * v.y;
        float4 a0 = att4[i][0], a1 = att4[i][1];
        float a[Kk] = { a0.x, a0.y, a0.z, a0.w, a1.x, a1.y, a1.z, a1.w };
        #pragma unroll
        for (int k = 0; k < Kk; k++) {
            mu_[k][0] += a[k] * v.x;  mu_[k][1] += a[k] * v.y;
            v2_[k][0] += a[k] * vx2;  v2_[k][1] += a[k] * vy2;
        }
    }
    #pragma unroll
    for (int k = 0; k < Kk; k++) {
        size_t idx = (((size_t)nc * Bb + b) * Kk + k) * Dd + d0;
        *(float2*)(g_mupart + idx) = make_float2(mu_[k][0], mu_[k][1]);
        *(float2*)(g_v2part + idx) = make_float2(v2_[k][0], v2_[k][1]);
    }
}

// ---------------- K6: reduce; update + next prep; final -> outputs -----------
__global__ void reduce_update(int final_it, const float* __restrict__ noise_final,
                              float* __restrict__ out) {
    int bk_ = blockIdx.x;
    int b = bk_ >> 3, k = bk_ & 7;
    int t = threadIdx.x;
    float S = 0.f;
    #pragma unroll
    for (int c = 0; c < NROWCHUNK; c++)
        S += g_Spart[((size_t)b * NROWCHUNK + c) * Kk + k];   // fixed order
    float denom = S + c_EPS;
    float s = S / denom;
    float slog = 0.f, sqwq = 0.f;
    for (int d = t; d < Dd; d += 128) {
        float m = 0.f, v2 = 0.f;
        #pragma unroll
        for (int c = 0; c < NCHUNK; c++) {
            size_t idx = (((size_t)c * Bb + b) * Kk + k) * Dd + d;
            m  += g_mupart[idx];
            v2 += g_v2part[idx];
        }
        m  /= denom;
        v2 /= denom;
        float sg = v2 - m * m * (2.f - s);
        if (final_it) {
            float sa = fmaxf(fabsf(sg), c_EPS);
            out[(size_t)bk_ * Dd + d] = m + sa * noise_final[(size_t)bk_ * Dd + d];
        } else {
            float w = 1.f / (sg * sg + c_EPS);
            float q = g_q[(size_t)bk_ * Dd + d];
            g_wq[(size_t)bk_ * Dd + d] = make_float2(w, q * w);
            slog += logf(fabsf(sg) + c_EPS);
            sqwq += q * q * w;
        }
    }
    if (final_it) {
        float* ao = out + Bb * Kk * Dd + ((size_t)b * Kk + k) * Nn;
        float inv = 1.f / denom;
        for (int n = t; n < Nn; n += 128)
            ao[n] = g_attn[((size_t)b * Nn + n) * Kk + k] * inv;
        return;
    }
    #pragma unroll
    for (int o = 16; o; o >>= 1) {
        slog += __shfl_xor_sync(0xffffffffu, slog, o);
        sqwq += __shfl_xor_sync(0xffffffffu, sqwq, o);
    }
    __shared__ float sh[2][4];
    if ((t & 31) == 0) { sh[0][t >> 5] = slog; sh[1][t >> 5] = sqwq; }
    __syncthreads();
    if (t == 0) {
        float SL = sh[0][0] + sh[0][1] + sh[0][2] + sh[0][3];
        float SQ = sh[1][0] + sh[1][1] + sh[1][2] + sh[1][3];
        g_c1[bk_] = -0.5f * (float)Dd * c_LOG2PI - 0.5f * SL - 0.5f * SQ;
        g_mixing[bk_] = s / (float)Nn;
    }
}

// ---------------- launcher ---------------------------------------------------
extern "C" void kernel_launch(void* const* d_in, const int* in_sizes, int n_in,
                              void* d_out, int out_size) {
    const float* embeddings = (const float*)d_in[0];
    const float* noise_init = (const float*)d_in[1];
    const float* noise_final= (const float*)d_in[2];
    const float* slots_mu   = (const float*)d_in[3];
    const float* slots_ls   = (const float*)d_in[4];
    const float* mixing     = (const float*)d_in[5];
    const float* Wk = (const float*)d_in[6];
    const float* bk = (const float*)d_in[7];
    const float* Wq = (const float*)d_in[8];
    const float* bq = (const float*)d_in[9];
    const float* Wv = (const float*)d_in[10];
    const float* bv = (const float*)d_in[11];
    const float* lng = (const float*)d_in[12];
    const float* lnb = (const float*)d_in[13];
    float* out = (float*)d_out;

    cudaFuncSetAttribute(mma_kv, cudaFuncAttributeMaxDynamicSharedMemorySize, MMA_SMEM);

    ln_split<<<Mtot, 128>>>(embeddings, lng, lnb);
    wt_split<<<dim3(32, 16), dim3(32, 8)>>>(Wk, Wv);
    init_slots_queries<<<Bb * Kk, 128>>>(noise_init, slots_mu, slots_ls, mixing, Wq, bq);
    mma_kv<<<dim3(Ntot / 128, Mtot / 128), 256, MMA_SMEM>>>(bk, bv);

    for (int it = 0; it < NITER; it++) {
        gll_attn<<<dim3(Bb, NROWCHUNK), 256>>>();
        mu_partial<<<dim3(Bb, 2, NCHUNK), 128>>>();
        reduce_update<<<Bb * Kk, 128>>>(it == NITER - 1 ? 1 : 0, noise_final, out);
    }
}